// round 12
// baseline (speedup 1.0000x reference)
#include <cuda_runtime.h>
#include <cuda_bf16.h>
#include <cstdint>

#define N_NODES 100000
#define N_EDGES 1600000
#define IN_F    512
#define OUT_F   64
#define QRT_E   (N_EDGES / 4)

// ---- scratch (__device__ globals) ------------------------------------------
__device__ float    g_h[(size_t)N_NODES * OUT_F];   // projected features
__device__ float    g_deg[N_NODES];                 // in-degree per dst node
// W pre-split, packed bf16 pairs along k: [kpair][n]
__device__ unsigned g_Bhi[(IN_F / 2) * OUT_F];
__device__ unsigned g_Blo[(IN_F / 2) * OUT_F];

// ---- bf16 split helpers ------------------------------------------------------
__device__ __forceinline__ void split_bf16(float x, __nv_bfloat16& hi, __nv_bfloat16& lo) {
    hi = __float2bfloat16_rn(x);
    lo = __float2bfloat16_rn(x - __bfloat162float(hi));
}
__device__ __forceinline__ unsigned pack_bf16(__nv_bfloat16 a, __nv_bfloat16 b) {
    unsigned short ua = *reinterpret_cast<unsigned short*>(&a);
    unsigned short ub = *reinterpret_cast<unsigned short*>(&b);
    return (unsigned)ua | ((unsigned)ub << 16);
}

__device__ __forceinline__ void mma16(float& d0, float& d1, float& d2, float& d3,
                                      unsigned a0, unsigned a1, unsigned a2, unsigned a3,
                                      unsigned b0, unsigned b1) {
    asm volatile("mma.sync.aligned.m16n8k16.row.col.f32.bf16.bf16.f32 "
                 "{%0,%1,%2,%3},{%4,%5,%6,%7},{%8,%9},{%0,%1,%2,%3};"
                 : "+f"(d0), "+f"(d1), "+f"(d2), "+f"(d3)
                 : "r"(a0), "r"(a1), "r"(a2), "r"(a3), "r"(b0), "r"(b1));
}

// ---------------------------------------------------------------------------
// 0) fused init: zero out + deg, pre-split W
// ---------------------------------------------------------------------------
__global__ void init_kernel(float4* __restrict__ out4, const float* __restrict__ W) {
    const int i = blockIdx.x * blockDim.x + threadIdx.x;
    if (i < N_NODES * OUT_F / 4) out4[i] = make_float4(0.f, 0.f, 0.f, 0.f);
    if (i < N_NODES) g_deg[i] = 0.0f;
    if (i < (IN_F / 2) * OUT_F) {
        const int kp = i >> 6;
        const int n  = i & 63;
        const float x0 = W[(size_t)(2 * kp)     * OUT_F + n];
        const float x1 = W[(size_t)(2 * kp + 1) * OUT_F + n];
        __nv_bfloat16 h0, l0, h1, l1;
        split_bf16(x0, h0, l0);
        split_bf16(x1, h1, l1);
        g_Bhi[i] = pack_bf16(h0, h1);
        g_Blo[i] = pack_bf16(l0, l1);
    }
}

// ---------------------------------------------------------------------------
// 1) GEMM (bf16 tensor cores, 3xBF16 compensated), A AND B register prefetch.
//    Block 128x64, 8 warps (4m x 2n), warp tile 32x32, KC=32 (2 x k16).
// ---------------------------------------------------------------------------
__global__ __launch_bounds__(256) void gemm_bf16_kernel(
    const float* __restrict__ feat)
{
    __shared__ unsigned As_hi[128][20];
    __shared__ unsigned As_lo[128][20];
    __shared__ unsigned Bs_hi[16][72];
    __shared__ unsigned Bs_lo[16][72];

    const int tid  = threadIdx.x;
    const int wid  = tid >> 5;
    const int lane = tid & 31;
    const int wm   = wid >> 1;
    const int wn   = wid & 1;
    const int gid  = lane >> 2;
    const int tig  = lane & 3;
    const int m0   = blockIdx.x * 128;

    // A loader mapping: 4 float4 chunks per thread
    const int lr[4] = { (tid) >> 3, (tid + 256) >> 3, (tid + 512) >> 3, (tid + 768) >> 3 };
    const int lf    = tid & 7;
    // B loader mapping: 1 uint4 per thread per array
    const int bkp = tid >> 4;
    const int bn4 = (tid & 15) * 4;

    float acc[2][4][4] = {};
    float4 ra[4];
    uint4  rbh, rbl;

    // prologue: load tile 0 into regs
    #pragma unroll
    for (int q = 0; q < 4; q++) {
        ra[q] = make_float4(0.f, 0.f, 0.f, 0.f);
        if (m0 + lr[q] < N_NODES)
            ra[q] = *reinterpret_cast<const float4*>(feat + (size_t)(m0 + lr[q]) * IN_F + lf * 4);
    }
    {
        const size_t gidx = (size_t)bkp * OUT_F + bn4;
        rbh = *reinterpret_cast<const uint4*>(g_Bhi + gidx);
        rbl = *reinterpret_cast<const uint4*>(g_Blo + gidx);
    }

    for (int k0 = 0; k0 < IN_F; k0 += 32) {
        // store prefetched A (split) + B to smem
        #pragma unroll
        for (int q = 0; q < 4; q++) {
            __nv_bfloat16 hx, lx, hy, ly, hz, lz, hw, lw;
            split_bf16(ra[q].x, hx, lx); split_bf16(ra[q].y, hy, ly);
            split_bf16(ra[q].z, hz, lz); split_bf16(ra[q].w, hw, lw);
            As_hi[lr[q]][lf * 2]     = pack_bf16(hx, hy);
            As_hi[lr[q]][lf * 2 + 1] = pack_bf16(hz, hw);
            As_lo[lr[q]][lf * 2]     = pack_bf16(lx, ly);
            As_lo[lr[q]][lf * 2 + 1] = pack_bf16(lz, lw);
        }
        *reinterpret_cast<uint4*>(&Bs_hi[bkp][bn4]) = rbh;
        *reinterpret_cast<uint4*>(&Bs_lo[bkp][bn4]) = rbl;
        __syncthreads();

        // prefetch next tile (A from DRAM, B from L2) — latency overlaps MMAs
        const int kn = k0 + 32;
        if (kn < IN_F) {
            #pragma unroll
            for (int q = 0; q < 4; q++) {
                ra[q] = make_float4(0.f, 0.f, 0.f, 0.f);
                if (m0 + lr[q] < N_NODES)
                    ra[q] = *reinterpret_cast<const float4*>(feat + (size_t)(m0 + lr[q]) * IN_F + kn + lf * 4);
            }
            const size_t gidx = (size_t)(kn / 2 + bkp) * OUT_F + bn4;
            rbh = *reinterpret_cast<const uint4*>(g_Bhi + gidx);
            rbl = *reinterpret_cast<const uint4*>(g_Blo + gidx);
        }

        #pragma unroll
        for (int kf = 0; kf < 2; kf++) {
            const int pb = kf * 8;
            unsigned ah[2][4], al[2][4];
            #pragma unroll
            for (int mf = 0; mf < 2; mf++) {
                const int r = wm * 32 + mf * 16 + gid;
                ah[mf][0] = As_hi[r][pb + tig];
                ah[mf][1] = As_hi[r + 8][pb + tig];
                ah[mf][2] = As_hi[r][pb + tig + 4];
                ah[mf][3] = As_hi[r + 8][pb + tig + 4];
                al[mf][0] = As_lo[r][pb + tig];
                al[mf][1] = As_lo[r + 8][pb + tig];
                al[mf][2] = As_lo[r][pb + tig + 4];
                al[mf][3] = As_lo[r + 8][pb + tig + 4];
            }
            unsigned bh[4][2], bl[4][2];
            #pragma unroll
            for (int nf = 0; nf < 4; nf++) {
                const int c = wn * 32 + nf * 8 + gid;
                bh[nf][0] = Bs_hi[pb + tig][c];
                bh[nf][1] = Bs_hi[pb + tig + 4][c];
                bl[nf][0] = Bs_lo[pb + tig][c];
                bl[nf][1] = Bs_lo[pb + tig + 4][c];
            }
            #pragma unroll
            for (int mf = 0; mf < 2; mf++)
                #pragma unroll
                for (int nf = 0; nf < 4; nf++) {
                    float* d = acc[mf][nf];
                    mma16(d[0], d[1], d[2], d[3],
                          ah[mf][0], ah[mf][1], ah[mf][2], ah[mf][3],
                          bh[nf][0], bh[nf][1]);
                    mma16(d[0], d[1], d[2], d[3],
                          ah[mf][0], ah[mf][1], ah[mf][2], ah[mf][3],
                          bl[nf][0], bl[nf][1]);
                    mma16(d[0], d[1], d[2], d[3],
                          al[mf][0], al[mf][1], al[mf][2], al[mf][3],
                          bh[nf][0], bh[nf][1]);
                }
        }
        __syncthreads();
    }

    #pragma unroll
    for (int mf = 0; mf < 2; mf++) {
        #pragma unroll
        for (int nf = 0; nf < 4; nf++) {
            const int c  = wn * 32 + nf * 8 + tig * 2;
            const int r0 = m0 + wm * 32 + mf * 16 + gid;
            if (r0 < N_NODES)
                *reinterpret_cast<float2*>(g_h + (size_t)r0 * OUT_F + c) =
                    make_float2(acc[mf][nf][0], acc[mf][nf][1]);
            if (r0 + 8 < N_NODES)
                *reinterpret_cast<float2*>(g_h + (size_t)(r0 + 8) * OUT_F + c) =
                    make_float2(acc[mf][nf][2], acc[mf][nf][3]);
        }
    }
}

// ---------------------------------------------------------------------------
// 2) Edge scatter, MLP=4 (unchanged from R11)
// ---------------------------------------------------------------------------
__global__ __launch_bounds__(256) void edge_kernel(
    const int* __restrict__ src, const int* __restrict__ dst,
    const float* __restrict__ ew, float* __restrict__ out)
{
    const long long t = (long long)blockIdx.x * blockDim.x + threadIdx.x;
    const int e0 = (int)(t >> 4);
    const int l  = (int)(t & 15);
    if (e0 >= QRT_E) return;

    int   s[4], d[4];
    float w[4];
    #pragma unroll
    for (int q = 0; q < 4; q++) {
        const int e = e0 + q * QRT_E;
        s[q] = __ldg(src + e);
        d[q] = __ldg(dst + e);
        w[q] = __ldg(ew  + e);
    }

    float4 v[4];
    #pragma unroll
    for (int q = 0; q < 4; q++)
        v[q] = *reinterpret_cast<const float4*>(g_h + (size_t)s[q] * OUT_F + l * 4);

    #pragma unroll
    for (int q = 0; q < 4; q++) {
        v[q].x *= w[q]; v[q].y *= w[q]; v[q].z *= w[q]; v[q].w *= w[q];
        float* p = out + (size_t)d[q] * OUT_F + l * 4;
        asm volatile("red.global.add.v4.f32 [%0], {%1,%2,%3,%4};"
                     :: "l"(p), "f"(v[q].x), "f"(v[q].y), "f"(v[q].z), "f"(v[q].w)
                     : "memory");
    }

    if (l == 0) {
        #pragma unroll
        for (int q = 0; q < 4; q++) atomicAdd(&g_deg[d[q]], 1.0f);
    }
}

// ---------------------------------------------------------------------------
// 3) finalize, MLP=2: each thread does 2 float4 of the SAME node.
// ---------------------------------------------------------------------------
__global__ void finalize_kernel(float4* __restrict__ out4, const float* __restrict__ bias) {
    const int i = blockIdx.x * blockDim.x + threadIdx.x;    // over N*OUT_F/8
    if (i >= N_NODES * OUT_F / 8) return;
    const int node = i >> 3;
    const int c8   = (i & 7) * 8;                           // column base (2 float4)
    const float dg = g_deg[node];
    const float rinv = (dg > 0.0f) ? (1.0f / dg) : 0.0f;

    const int base = node * (OUT_F / 4) + c8 / 4;
    float4 v0 = out4[base];
    float4 v1 = out4[base + 1];
    v0.x = fmaxf(fmaf(v0.x, rinv, __ldg(bias + c8 + 0)), 0.0f);
    v0.y = fmaxf(fmaf(v0.y, rinv, __ldg(bias + c8 + 1)), 0.0f);
    v0.z = fmaxf(fmaf(v0.z, rinv, __ldg(bias + c8 + 2)), 0.0f);
    v0.w = fmaxf(fmaf(v0.w, rinv, __ldg(bias + c8 + 3)), 0.0f);
    v1.x = fmaxf(fmaf(v1.x, rinv, __ldg(bias + c8 + 4)), 0.0f);
    v1.y = fmaxf(fmaf(v1.y, rinv, __ldg(bias + c8 + 5)), 0.0f);
    v1.z = fmaxf(fmaf(v1.z, rinv, __ldg(bias + c8 + 6)), 0.0f);
    v1.w = fmaxf(fmaf(v1.w, rinv, __ldg(bias + c8 + 7)), 0.0f);
    out4[base]     = v0;
    out4[base + 1] = v1;
}

// ---------------------------------------------------------------------------
extern "C" void kernel_launch(void* const* d_in, const int* in_sizes, int n_in,
                              void* d_out, int out_size)
{
    const float* feat     = (const float*)d_in[0];
    const float* edge_w   = (const float*)d_in[1];
    const float* weight   = (const float*)d_in[2];
    const float* bias     = (const float*)d_in[3];
    const int*   edge_src = (const int*)d_in[4];
    const int*   edge_dst = (const int*)d_in[5];
    float* out = (float*)d_out;

    init_kernel<<<(N_NODES * OUT_F / 4 + 255) / 256, 256>>>((float4*)out, weight);
    gemm_bf16_kernel<<<(N_NODES + 127) / 128, 256>>>(feat);
    edge_kernel<<<(int)(((long long)QRT_E * 16 + 255) / 256), 256>>>(edge_src, edge_dst, edge_w, out);
    finalize_kernel<<<(N_NODES * OUT_F / 8 + 255) / 256, 256>>>((float4*)out, bias);
}

// round 13
// speedup vs baseline: 1.0219x; 1.0219x over previous
#include <cuda_runtime.h>
#include <cuda_bf16.h>
#include <cstdint>

#define N_NODES 100000
#define N_EDGES 1600000
#define IN_F    512
#define OUT_F   64
#define QRT_E   (N_EDGES / 4)

// ---- scratch (__device__ globals) ------------------------------------------
__device__ float    g_h[(size_t)N_NODES * OUT_F];   // projected features
__device__ float    g_deg[N_NODES];                 // in-degree per dst node
// W pre-split, packed bf16 pairs along k: [kpair][n]
__device__ unsigned g_Bhi[(IN_F / 2) * OUT_F];
__device__ unsigned g_Blo[(IN_F / 2) * OUT_F];

// ---- bf16 split helpers ------------------------------------------------------
__device__ __forceinline__ void split_bf16(float x, __nv_bfloat16& hi, __nv_bfloat16& lo) {
    hi = __float2bfloat16_rn(x);
    lo = __float2bfloat16_rn(x - __bfloat162float(hi));
}
__device__ __forceinline__ unsigned pack_bf16(__nv_bfloat16 a, __nv_bfloat16 b) {
    unsigned short ua = *reinterpret_cast<unsigned short*>(&a);
    unsigned short ub = *reinterpret_cast<unsigned short*>(&b);
    return (unsigned)ua | ((unsigned)ub << 16);
}

__device__ __forceinline__ void mma16(float& d0, float& d1, float& d2, float& d3,
                                      unsigned a0, unsigned a1, unsigned a2, unsigned a3,
                                      unsigned b0, unsigned b1) {
    asm volatile("mma.sync.aligned.m16n8k16.row.col.f32.bf16.bf16.f32 "
                 "{%0,%1,%2,%3},{%4,%5,%6,%7},{%8,%9},{%0,%1,%2,%3};"
                 : "+f"(d0), "+f"(d1), "+f"(d2), "+f"(d3)
                 : "r"(a0), "r"(a1), "r"(a2), "r"(a3), "r"(b0), "r"(b1));
}

// smem pipeline layout (unsigned element counts)
#define A_CNT   (128 * 20)                    // As_hi or As_lo
#define B_CNT   (16 * 72)                     // Bs_hi or Bs_lo
#define BUF_CNT (2 * A_CNT + 2 * B_CNT)       // one stage
#define GEMM_SMEM_BYTES (2 * BUF_CNT * (int)sizeof(unsigned))
#define OFF_AHI 0
#define OFF_ALO A_CNT
#define OFF_BHI (2 * A_CNT)
#define OFF_BLO (2 * A_CNT + B_CNT)

// ---------------------------------------------------------------------------
// 0) fused init: zero out + deg, pre-split W
// ---------------------------------------------------------------------------
__global__ void init_kernel(float4* __restrict__ out4, const float* __restrict__ W) {
    const int i = blockIdx.x * blockDim.x + threadIdx.x;
    if (i < N_NODES * OUT_F / 4) out4[i] = make_float4(0.f, 0.f, 0.f, 0.f);
    if (i < N_NODES) g_deg[i] = 0.0f;
    if (i < (IN_F / 2) * OUT_F) {
        const int kp = i >> 6;
        const int n  = i & 63;
        const float x0 = W[(size_t)(2 * kp)     * OUT_F + n];
        const float x1 = W[(size_t)(2 * kp + 1) * OUT_F + n];
        __nv_bfloat16 h0, l0, h1, l1;
        split_bf16(x0, h0, l0);
        split_bf16(x1, h1, l1);
        g_Bhi[i] = pack_bf16(h0, h1);
        g_Blo[i] = pack_bf16(l0, l1);
    }
}

// ---------------------------------------------------------------------------
// 1) GEMM (bf16 tensor cores, 3xBF16), 2-stage smem pipeline, 1 sync/iter.
//    Block 128x64, 8 warps (4m x 2n), warp tile 32x32, KC=32 (2 x k16).
// ---------------------------------------------------------------------------
__global__ __launch_bounds__(256) void gemm_bf16_kernel(
    const float* __restrict__ feat)
{
    extern __shared__ unsigned sm[];

    const int tid  = threadIdx.x;
    const int wid  = tid >> 5;
    const int lane = tid & 31;
    const int wm   = wid >> 1;
    const int wn   = wid & 1;
    const int gid  = lane >> 2;
    const int tig  = lane & 3;
    const int m0   = blockIdx.x * 128;

    // A loader mapping: 4 float4 chunks per thread
    const int lr[4] = { (tid) >> 3, (tid + 256) >> 3, (tid + 512) >> 3, (tid + 768) >> 3 };
    const int lf    = tid & 7;
    // B loader mapping: 1 uint4 per thread per array
    const int bkp = tid >> 4;
    const int bn4 = (tid & 15) * 4;

    float acc[2][4][4] = {};
    float4 ra[4];
    uint4  rbh, rbl;

    // prologue: load tile 0 into regs
    #pragma unroll
    for (int q = 0; q < 4; q++) {
        ra[q] = make_float4(0.f, 0.f, 0.f, 0.f);
        if (m0 + lr[q] < N_NODES)
            ra[q] = *reinterpret_cast<const float4*>(feat + (size_t)(m0 + lr[q]) * IN_F + lf * 4);
    }
    {
        const size_t gidx = (size_t)bkp * OUT_F + bn4;
        rbh = *reinterpret_cast<const uint4*>(g_Bhi + gidx);
        rbl = *reinterpret_cast<const uint4*>(g_Blo + gidx);
    }

    // pipeline: iteration it stores tile it, prefetches tile it+1, MMAs tile it-1
    #pragma unroll 1
    for (int it = 0; it <= IN_F / 32; it++) {
        if (it < IN_F / 32) {
            unsigned* bw = sm + (it & 1) * BUF_CNT;
            // split + store A (tile it)
            #pragma unroll
            for (int q = 0; q < 4; q++) {
                __nv_bfloat16 hx, lx, hy, ly, hz, lz, hw, lw;
                split_bf16(ra[q].x, hx, lx); split_bf16(ra[q].y, hy, ly);
                split_bf16(ra[q].z, hz, lz); split_bf16(ra[q].w, hw, lw);
                bw[OFF_AHI + lr[q] * 20 + lf * 2]     = pack_bf16(hx, hy);
                bw[OFF_AHI + lr[q] * 20 + lf * 2 + 1] = pack_bf16(hz, hw);
                bw[OFF_ALO + lr[q] * 20 + lf * 2]     = pack_bf16(lx, ly);
                bw[OFF_ALO + lr[q] * 20 + lf * 2 + 1] = pack_bf16(lz, lw);
            }
            // store B (tile it)
            *reinterpret_cast<uint4*>(&bw[OFF_BHI + bkp * 72 + bn4]) = rbh;
            *reinterpret_cast<uint4*>(&bw[OFF_BLO + bkp * 72 + bn4]) = rbl;

            // prefetch tile it+1 into regs
            const int kn = (it + 1) * 32;
            if (kn < IN_F) {
                #pragma unroll
                for (int q = 0; q < 4; q++) {
                    ra[q] = make_float4(0.f, 0.f, 0.f, 0.f);
                    if (m0 + lr[q] < N_NODES)
                        ra[q] = *reinterpret_cast<const float4*>(feat + (size_t)(m0 + lr[q]) * IN_F + kn + lf * 4);
                }
                const size_t gidx = (size_t)(kn / 2 + bkp) * OUT_F + bn4;
                rbh = *reinterpret_cast<const uint4*>(g_Bhi + gidx);
                rbl = *reinterpret_cast<const uint4*>(g_Blo + gidx);
            }
        }

        if (it > 0) {
            const unsigned* br = sm + ((it - 1) & 1) * BUF_CNT;
            #pragma unroll
            for (int kf = 0; kf < 2; kf++) {
                const int pb = kf * 8;
                unsigned ah[2][4], al[2][4];
                #pragma unroll
                for (int mf = 0; mf < 2; mf++) {
                    const int r = wm * 32 + mf * 16 + gid;
                    ah[mf][0] = br[OFF_AHI + r * 20 + pb + tig];
                    ah[mf][1] = br[OFF_AHI + (r + 8) * 20 + pb + tig];
                    ah[mf][2] = br[OFF_AHI + r * 20 + pb + tig + 4];
                    ah[mf][3] = br[OFF_AHI + (r + 8) * 20 + pb + tig + 4];
                    al[mf][0] = br[OFF_ALO + r * 20 + pb + tig];
                    al[mf][1] = br[OFF_ALO + (r + 8) * 20 + pb + tig];
                    al[mf][2] = br[OFF_ALO + r * 20 + pb + tig + 4];
                    al[mf][3] = br[OFF_ALO + (r + 8) * 20 + pb + tig + 4];
                }
                unsigned bh[4][2], bl[4][2];
                #pragma unroll
                for (int nf = 0; nf < 4; nf++) {
                    const int c = wn * 32 + nf * 8 + gid;
                    bh[nf][0] = br[OFF_BHI + (pb + tig) * 72 + c];
                    bh[nf][1] = br[OFF_BHI + (pb + tig + 4) * 72 + c];
                    bl[nf][0] = br[OFF_BLO + (pb + tig) * 72 + c];
                    bl[nf][1] = br[OFF_BLO + (pb + tig + 4) * 72 + c];
                }
                #pragma unroll
                for (int mf = 0; mf < 2; mf++)
                    #pragma unroll
                    for (int nf = 0; nf < 4; nf++) {
                        float* d = acc[mf][nf];
                        mma16(d[0], d[1], d[2], d[3],
                              ah[mf][0], ah[mf][1], ah[mf][2], ah[mf][3],
                              bh[nf][0], bh[nf][1]);
                        mma16(d[0], d[1], d[2], d[3],
                              ah[mf][0], ah[mf][1], ah[mf][2], ah[mf][3],
                              bl[nf][0], bl[nf][1]);
                        mma16(d[0], d[1], d[2], d[3],
                              al[mf][0], al[mf][1], al[mf][2], al[mf][3],
                              bh[nf][0], bh[nf][1]);
                    }
            }
        }
        __syncthreads();
    }

    #pragma unroll
    for (int mf = 0; mf < 2; mf++) {
        #pragma unroll
        for (int nf = 0; nf < 4; nf++) {
            const int c  = wn * 32 + nf * 8 + tig * 2;
            const int r0 = m0 + wm * 32 + mf * 16 + gid;
            if (r0 < N_NODES)
                *reinterpret_cast<float2*>(g_h + (size_t)r0 * OUT_F + c) =
                    make_float2(acc[mf][nf][0], acc[mf][nf][1]);
            if (r0 + 8 < N_NODES)
                *reinterpret_cast<float2*>(g_h + (size_t)(r0 + 8) * OUT_F + c) =
                    make_float2(acc[mf][nf][2], acc[mf][nf][3]);
        }
    }
}

// ---------------------------------------------------------------------------
// 2) Edge scatter, MLP=4 (unchanged from R11)
// ---------------------------------------------------------------------------
__global__ __launch_bounds__(256) void edge_kernel(
    const int* __restrict__ src, const int* __restrict__ dst,
    const float* __restrict__ ew, float* __restrict__ out)
{
    const long long t = (long long)blockIdx.x * blockDim.x + threadIdx.x;
    const int e0 = (int)(t >> 4);
    const int l  = (int)(t & 15);
    if (e0 >= QRT_E) return;

    int   s[4], d[4];
    float w[4];
    #pragma unroll
    for (int q = 0; q < 4; q++) {
        const int e = e0 + q * QRT_E;
        s[q] = __ldg(src + e);
        d[q] = __ldg(dst + e);
        w[q] = __ldg(ew  + e);
    }

    float4 v[4];
    #pragma unroll
    for (int q = 0; q < 4; q++)
        v[q] = *reinterpret_cast<const float4*>(g_h + (size_t)s[q] * OUT_F + l * 4);

    #pragma unroll
    for (int q = 0; q < 4; q++) {
        v[q].x *= w[q]; v[q].y *= w[q]; v[q].z *= w[q]; v[q].w *= w[q];
        float* p = out + (size_t)d[q] * OUT_F + l * 4;
        asm volatile("red.global.add.v4.f32 [%0], {%1,%2,%3,%4};"
                     :: "l"(p), "f"(v[q].x), "f"(v[q].y), "f"(v[q].z), "f"(v[q].w)
                     : "memory");
    }

    if (l == 0) {
        #pragma unroll
        for (int q = 0; q < 4; q++) atomicAdd(&g_deg[d[q]], 1.0f);
    }
}

// ---------------------------------------------------------------------------
// 3) finalize (vectorized, R11 version): out = relu(msum * rinv + bias)
// ---------------------------------------------------------------------------
__global__ void finalize_kernel(float4* __restrict__ out4, const float* __restrict__ bias) {
    const int i = blockIdx.x * blockDim.x + threadIdx.x;
    if (i >= N_NODES * OUT_F / 4) return;
    const int node = i >> 4;
    const int c4   = (i & 15) * 4;
    const float d  = g_deg[node];
    const float rinv = (d > 0.0f) ? (1.0f / d) : 0.0f;
    float4 v = out4[i];
    v.x = fmaxf(fmaf(v.x, rinv, __ldg(bias + c4 + 0)), 0.0f);
    v.y = fmaxf(fmaf(v.y, rinv, __ldg(bias + c4 + 1)), 0.0f);
    v.z = fmaxf(fmaf(v.z, rinv, __ldg(bias + c4 + 2)), 0.0f);
    v.w = fmaxf(fmaf(v.w, rinv, __ldg(bias + c4 + 3)), 0.0f);
    out4[i] = v;
}

// ---------------------------------------------------------------------------
extern "C" void kernel_launch(void* const* d_in, const int* in_sizes, int n_in,
                              void* d_out, int out_size)
{
    const float* feat     = (const float*)d_in[0];
    const float* edge_w   = (const float*)d_in[1];
    const float* weight   = (const float*)d_in[2];
    const float* bias     = (const float*)d_in[3];
    const int*   edge_src = (const int*)d_in[4];
    const int*   edge_dst = (const int*)d_in[5];
    float* out = (float*)d_out;

    cudaFuncSetAttribute(gemm_bf16_kernel,
                         cudaFuncAttributeMaxDynamicSharedMemorySize, GEMM_SMEM_BYTES);

    init_kernel<<<(N_NODES * OUT_F / 4 + 255) / 256, 256>>>((float4*)out, weight);
    gemm_bf16_kernel<<<(N_NODES + 127) / 128, 256, GEMM_SMEM_BYTES>>>(feat);
    edge_kernel<<<(int)(((long long)QRT_E * 16 + 255) / 256), 256>>>(edge_src, edge_dst, edge_w, out);
    finalize_kernel<<<(N_NODES * OUT_F / 4 + 255) / 256, 256>>>((float4*)out, bias);
}